// round 2
// baseline (speedup 1.0000x reference)
#include <cuda_runtime.h>
#include <math.h>

#define NN  50000
#define EE  1250000
#define DIMM 64
#define HHH 16

// Scratch (device globals; no runtime allocation). float4 layout: [node][head] = 16B
__device__ float4 g_q[NN * HHH];
__device__ float4 g_k[NN * HHH];
__device__ float4 g_v[NN * HHH];
__device__ float  g_dot[NN * DIMM];
__device__ float4 g_agg[NN * HHH];

// ---------------------------------------------------------------------------
// K1: LayerNorm + QKV projection. 192 threads/block, each thread owns one
// output column of qkv_w held in 64 registers; activations broadcast via smem.
// ---------------------------------------------------------------------------
__global__ void __launch_bounds__(192) qkv_kernel(
    const float* __restrict__ node_feat,
    const float* __restrict__ ln_g, const float* __restrict__ ln_b,
    const float* __restrict__ qkv_w, const float* __restrict__ qkv_b)
{
    __shared__ float sx[64];
    __shared__ float sxn[64];
    const int t = threadIdx.x;  // 0..191

    float wc[64];
#pragma unroll
    for (int k = 0; k < 64; k++) wc[k] = qkv_w[k * 192 + t];
    const float bc = qkv_b[t];
    const float gg = (t < 64) ? ln_g[t] : 0.f;
    const float bb = (t < 64) ? ln_b[t] : 0.f;

    const int h = t / 12;
    const int r = t % 12;

    for (int n = blockIdx.x; n < NN; n += gridDim.x) {
        if (t < 64) sx[t] = node_feat[n * 64 + t];
        __syncthreads();
        float s = 0.f, s2 = 0.f;
#pragma unroll
        for (int k = 0; k < 64; k++) { float xv = sx[k]; s += xv; s2 += xv * xv; }
        const float mu   = s * (1.f / 64.f);
        const float var  = s2 * (1.f / 64.f) - mu * mu;
        const float rstd = rsqrtf(var + 1e-5f);
        if (t < 64) sxn[t] = (sx[t] - mu) * rstd * gg + bb;
        __syncthreads();

        float acc = bc;
#pragma unroll
        for (int k = 0; k < 64; k++) acc += sxn[k] * wc[k];

        float* base;
        int    d;
        if (r < 4)      { base = (float*)g_q; d = r; }
        else if (r < 8) { base = (float*)g_k; d = r - 4; }
        else            { base = (float*)g_v; d = r - 8; }
        base[(n * 16 + h) * 4 + d] = acc;
        __syncthreads();
    }
}

// ---------------------------------------------------------------------------
// K2: iv = node_vec @ vec_w ; input_dot = sum_a iv[:, :64]*iv[:, 64:]
// 128 threads/block; thread t owns column t of vec_w in 64 registers.
// ---------------------------------------------------------------------------
__global__ void __launch_bounds__(128) vec_kernel(
    const float* __restrict__ node_vec,
    const float* __restrict__ vec_w)
{
    __shared__ float nv[192];
    __shared__ float iv_s[3 * 128];
    const int t = threadIdx.x;  // 0..127

    float wc[64];
#pragma unroll
    for (int k = 0; k < 64; k++) wc[k] = vec_w[k * 128 + t];

    for (int n = blockIdx.x; n < NN; n += gridDim.x) {
        if (t < 96) {
            nv[t]      = node_vec[n * 192 + t];
            nv[t + 96] = node_vec[n * 192 + t + 96];
        }
        __syncthreads();
#pragma unroll
        for (int a = 0; a < 3; a++) {
            float acc = 0.f;
#pragma unroll
            for (int k = 0; k < 64; k++) acc += nv[a * 64 + k] * wc[k];
            iv_s[a * 128 + t] = acc;
        }
        __syncthreads();
        if (t < 64) {
            float d = 0.f;
#pragma unroll
            for (int a = 0; a < 3; a++)
                d += iv_s[a * 128 + t] * iv_s[a * 128 + 64 + t];
            g_dot[n * 64 + t] = d;
        }
        __syncthreads();
    }
}

// ---------------------------------------------------------------------------
// Kz: zero the aggregation buffer
// ---------------------------------------------------------------------------
__global__ void zero_kernel()
{
    int i = blockIdx.x * blockDim.x + threadIdx.x;
    if (i < NN * HHH) g_agg[i] = make_float4(0.f, 0.f, 0.f, 0.f);
}

// ---------------------------------------------------------------------------
// K3: edge phase. One thread per (edge, head): 4-wide q·k dot, exact-erf GELU,
// message = v[col]*edge_feat*attn, atomic scatter-add into row's slot.
// ---------------------------------------------------------------------------
__global__ void __launch_bounds__(256) edge_kernel(
    const float4* __restrict__ edge_feat,
    const float*  __restrict__ radial,
    const int*    __restrict__ row,
    const int*    __restrict__ col)
{
    const int gid = blockIdx.x * blockDim.x + threadIdx.x;
    if (gid >= EE * HHH) return;
    const int e = gid >> 4;
    const int h = gid & 15;

    const int r = __ldg(&row[e]);
    const int c = __ldg(&col[e]);

    const float4 qv = g_q[r * 16 + h];
    const float4 kv = g_k[c * 16 + h];
    float dot = qv.x * kv.x + qv.y * kv.y + qv.z * kv.z + qv.w * kv.w;

    // exact GELU: 0.5*x*(1+erf(x/sqrt(2)))
    const float attn = 0.5f * dot * (1.f + erff(dot * 0.70710678118654752f))
                     * __ldg(&radial[e]);

    const float4 vv = g_v[c * 16 + h];
    const float4 ef = edge_feat[e * 16 + h];

    float* agg = (float*)&g_agg[r * 16 + h];
    atomicAdd(agg + 0, vv.x * ef.x * attn);
    atomicAdd(agg + 1, vv.y * ef.y * attn);
    atomicAdd(agg + 2, vv.z * ef.z * attn);
    atomicAdd(agg + 3, vv.w * ef.w * attn);
}

// ---------------------------------------------------------------------------
// K4: out = agg @ out_w + out_b ; result = input_dot * out[:, :64] + out[:, 64:]
// 128 threads/block; thread t owns column t of out_w in 64 registers.
// ---------------------------------------------------------------------------
__global__ void __launch_bounds__(128) out_kernel(
    const float* __restrict__ out_w,
    const float* __restrict__ out_b,
    float* __restrict__ out)
{
    __shared__ float sa[64];
    __shared__ float so[128];
    const int t = threadIdx.x;  // 0..127

    float wc[64];
#pragma unroll
    for (int k = 0; k < 64; k++) wc[k] = out_w[k * 128 + t];
    const float bc = out_b[t];

    const float* agg = (const float*)g_agg;
    for (int n = blockIdx.x; n < NN; n += gridDim.x) {
        if (t < 64) sa[t] = agg[n * 64 + t];
        __syncthreads();
        float acc = bc;
#pragma unroll
        for (int k = 0; k < 64; k++) acc += sa[k] * wc[k];
        so[t] = acc;
        __syncthreads();
        if (t < 64) out[n * 64 + t] = g_dot[n * 64 + t] * so[t] + so[64 + t];
        __syncthreads();
    }
}

// ---------------------------------------------------------------------------
// Inputs (metadata order):
//  0 node_feat (N,64) f32      1 edge_feat (E,16,4) f32   2 node_vec (N,3,64) f32
//  3 radial (E,) f32           4 ln_g (64,)               5 ln_b (64,)
//  6 qkv_w (64,192)            7 qkv_b (192,)             8 vec_w (64,128)
//  9 out_w (64,128)           10 out_b (128,)            11 row (E,) i32
// 12 col (E,) i32             13 natoms
// ---------------------------------------------------------------------------
extern "C" void kernel_launch(void* const* d_in, const int* in_sizes, int n_in,
                              void* d_out, int out_size)
{
    const float* node_feat = (const float*)d_in[0];
    const float* edge_feat = (const float*)d_in[1];
    const float* node_vec  = (const float*)d_in[2];
    const float* radial    = (const float*)d_in[3];
    const float* ln_g      = (const float*)d_in[4];
    const float* ln_b      = (const float*)d_in[5];
    const float* qkv_w     = (const float*)d_in[6];
    const float* qkv_b     = (const float*)d_in[7];
    const float* vec_w     = (const float*)d_in[8];
    const float* out_w     = (const float*)d_in[9];
    const float* out_b     = (const float*)d_in[10];
    const int*   row       = (const int*)d_in[11];
    const int*   col       = (const int*)d_in[12];
    float*       out       = (float*)d_out;

    qkv_kernel<<<2048, 192>>>(node_feat, ln_g, ln_b, qkv_w, qkv_b);
    vec_kernel<<<2048, 128>>>(node_vec, vec_w);
    zero_kernel<<<(NN * HHH + 255) / 256, 256>>>();
    edge_kernel<<<(EE * HHH + 255) / 256, 256>>>(
        (const float4*)edge_feat, radial, row, col);
    out_kernel<<<2048, 128>>>(out_w, out_b, out);
}